// round 16
// baseline (speedup 1.0000x reference)
#include <cuda_runtime.h>
#include <cstdint>

#define BB 64
#define RR 32
#define NN 16384
#define DD 64
#define OO 8
#define SLICES 8               // CTAs per cluster == slices per b
#define TPB 128
#define NWARP 4
#define SN (NN / SLICES)       // 2048 elements per slice-CTA
#define WCAP 64                // per-warp hit capacity (mean ~3.8)

__device__ __forceinline__ uint32_t smem_u32(const void* p) {
    return (uint32_t)__cvta_generic_to_shared(p);
}
__device__ __forceinline__ uint32_t ctarank() {
    uint32_t r; asm("mov.u32 %0, %%cluster_ctarank;" : "=r"(r)); return r;
}
__device__ __forceinline__ void st_cluster_f32(uint32_t laddr, uint32_t rank, float v) {
    uint32_t ra;
    asm volatile("mapa.shared::cluster.u32 %0, %1, %2;" : "=r"(ra) : "r"(laddr), "r"(rank));
    asm volatile("st.shared::cluster.f32 [%0], %1;" :: "r"(ra), "f"(v) : "memory");
}

// One cluster (8 CTAs) per b. Each CTA: warp-local scan+compact+gather of a
// 2048-element slice; partial -> rank0's smem via DSMEM; cluster barrier
// (release/acquire); rank0 reduces + epilogue. No global scratch, no fences.
__global__ void __launch_bounds__(TPB, 1) __cluster_dims__(SLICES, 1, 1)
fused_kernel(
    const float* __restrict__ h_context,
    const float* __restrict__ l_local,
    const float* __restrict__ lambda_so,
    const int* __restrict__ center_o,
    const int* __restrict__ o_types,
    const unsigned int* __restrict__ adj,   // bool as 32-bit word (i32/f32 0|1)
    const unsigned int* __restrict__ two,
    float* __restrict__ out)
{
    __shared__ int   s_widx[NWARP][WCAP];
    __shared__ int   s_wcnt[NWARP];
    __shared__ float s_part[NWARP][DD];
    __shared__ float red_buf[SLICES][DD];   // written via DSMEM into rank0
    __shared__ float red_cnt[SLICES];
    __shared__ float sv[DD];
    __shared__ float s_scnt;

    const int b    = blockIdx.x / SLICES;
    const int s    = blockIdx.x % SLICES;   // == cluster rank
    const int tid  = threadIdx.x;
    const int w    = tid >> 5;
    const int lane = tid & 31;

    const int co = __ldg(&center_o[b]);

    // ---- Phase A: streaming scan of slice (12 front-batched LDG.128) ----
    // uint4 index u = g*128 + tid (g = 0..3); element n = s*SN + u*4 + j.
    const int base = b * NN + s * SN;
    const int4*  ot4 = reinterpret_cast<const int4*>(o_types + base);
    const uint4* a4  = reinterpret_cast<const uint4*>(adj + base);
    const uint4* t4  = reinterpret_cast<const uint4*>(two + base);

    int4 ot[4]; uint4 aa[4]; uint4 tt[4];
    #pragma unroll
    for (int g = 0; g < 4; g++) ot[g] = ot4[g * TPB + tid];
    #pragma unroll
    for (int g = 0; g < 4; g++) aa[g] = a4[g * TPB + tid];
    #pragma unroll
    for (int g = 0; g < 4; g++) tt[g] = t4[g * TPB + tid];

    unsigned hm = 0;
    #pragma unroll
    for (int g = 0; g < 4; g++) {
        hm |= (unsigned)((ot[g].x == co) && (aa[g].x | tt[g].x)) << (g * 4 + 0);
        hm |= (unsigned)((ot[g].y == co) && (aa[g].y | tt[g].y)) << (g * 4 + 1);
        hm |= (unsigned)((ot[g].z == co) && (aa[g].z | tt[g].z)) << (g * 4 + 2);
        hm |= (unsigned)((ot[g].w == co) && (aa[g].w | tt[g].w)) << (g * 4 + 3);
    }

    // ---- Phase A2: warp-local shfl-prefix compaction ----
    int my = __popc(hm);
    int pre = my;
    #pragma unroll
    for (int o = 1; o < 32; o <<= 1) {
        int v = __shfl_up_sync(0xffffffffu, pre, o);
        if (lane >= o) pre += v;
    }
    const int wtot = __shfl_sync(0xffffffffu, pre, 31);
    int p = pre - my;
    unsigned m = hm;
    while (m) {
        int k = __ffs(m) - 1; m &= m - 1;
        int n = s * SN + ((k >> 2) * TPB + tid) * 4 + (k & 3);
        if (p < WCAP) s_widx[w][p] = n;
        p++;
    }
    __syncwarp();
    const int wcnt = (wtot < WCAP) ? wtot : WCAP;

    // ---- Phase B: warp gathers its own hits (4-row preload batches) ----
    const float2* ctx2 = reinterpret_cast<const float2*>(
        h_context + (size_t)b * NN * DD);
    float accx = 0.0f, accy = 0.0f;
    for (int bo = 0; bo < wcnt; bo += 4) {
        float2 xs[4];
        #pragma unroll
        for (int k = 0; k < 4; k++) {
            int i = bo + k;
            xs[k] = (i < wcnt)
                  ? __ldg(ctx2 + (size_t)s_widx[w][i] * (DD / 2) + lane)
                  : make_float2(0.0f, 0.0f);
        }
        #pragma unroll
        for (int k = 0; k < 4; k++) {
            float sq = xs[k].x * xs[k].x + xs[k].y * xs[k].y;
            #pragma unroll
            for (int o = 16; o; o >>= 1)
                sq += __shfl_xor_sync(0xffffffffu, sq, o);
            float rinv = rsqrtf(fmaxf(sq, 1e-12f));   // zero rows contribute 0
            accx += xs[k].x * rinv;
            accy += xs[k].y * rinv;
        }
    }
    s_part[w][2 * lane + 0] = accx;
    s_part[w][2 * lane + 1] = accy;
    if (lane == 0) s_wcnt[w] = wtot;
    __syncthreads();

    // ---- Publish CTA partial into rank0's red_buf via DSMEM ----
    const uint32_t rank = ctarank();   // == s
    if (tid < DD) {
        float lp = s_part[0][tid] + s_part[1][tid] + s_part[2][tid] + s_part[3][tid];
        st_cluster_f32(smem_u32(&red_buf[rank][tid]), 0, lp);
    }
    if (tid == DD) {
        float c = (float)(s_wcnt[0] + s_wcnt[1] + s_wcnt[2] + s_wcnt[3]);
        st_cluster_f32(smem_u32(&red_cnt[rank]), 0, c);
    }

    // Cluster barrier: arrive has release semantics (covers the DSMEM
    // stores above); wait has acquire (orders rank0's reads below).
    asm volatile("barrier.cluster.arrive.aligned;" ::: "memory");
    asm volatile("barrier.cluster.wait.aligned;" ::: "memory");

    if (rank != 0) return;

    // ---- Rank0: reduce 8 partials + epilogue ----
    if (tid < DD) {
        float v = 0.0f;
        #pragma unroll
        for (int ss = 0; ss < SLICES; ss++) v += red_buf[ss][tid];
        sv[tid] = v;
    }
    if (tid == 0) {
        float c = 0.0f;
        #pragma unroll
        for (int ss = 0; ss < SLICES; ss++) c += red_cnt[ss];
        s_scnt = c;
    }
    __syncthreads();

    const float cval = s_scnt;
    const float2* ll2 = reinterpret_cast<const float2*>(
        l_local + (size_t)b * RR * DD);
    #pragma unroll
    for (int rr = 0; rr < RR / NWARP; rr++) {
        int r = w + rr * NWARP;
        float2 x = __ldg(ll2 + (size_t)r * (DD / 2) + lane);
        float lam = __ldg(&lambda_so[r * OO + co]);
        float sq = x.x * x.x + x.y * x.y;
        float dp = x.x * sv[2 * lane] + x.y * sv[2 * lane + 1];
        #pragma unroll
        for (int o = 16; o; o >>= 1) {
            sq += __shfl_xor_sync(0xffffffffu, sq, o);
            dp += __shfl_xor_sync(0xffffffffu, dp, o);
        }
        if (lane == 0) {
            float rinv = rsqrtf(fmaxf(sq, 1e-12f));
            float avg = dp * rinv / fmaxf(cval, 1e-9f);
            float wv = fmaxf(lam / fmaxf(cval, 1.0f), 0.0f) * (1.0f - avg);
            out[b * RR + r] = wv;
        }
    }
}

extern "C" void kernel_launch(void* const* d_in, const int* in_sizes, int n_in,
                              void* d_out, int out_size) {
    const float*        l_local   = (const float*)d_in[0];
    const float*        h_context = (const float*)d_in[1];
    const float*        lambda_so = (const float*)d_in[2];
    const int*          center_o  = (const int*)d_in[3];
    const int*          o_types   = (const int*)d_in[4];
    const unsigned int* adj       = (const unsigned int*)d_in[5];
    const unsigned int* two       = (const unsigned int*)d_in[6];
    float*              out       = (float*)d_out;

    fused_kernel<<<BB * SLICES, TPB>>>(h_context, l_local, lambda_so,
                                       center_o, o_types, adj, two, out);
}

// round 17
// speedup vs baseline: 1.2179x; 1.2179x over previous
#include <cuda_runtime.h>
#include <cstdint>

#define BB 64
#define RR 32
#define NN 16384
#define DD 64
#define OO 8
#define TPB 1024
#define NWARP 32
#define WCAP 32                // per-warp hit capacity (mean ~3.8; P(>32) ~ 0)

// One block per b, 1024 threads, fully warp-local until the final combine.
// Phase A: stream ONLY adj+two (8 back-to-back LDG.128) -> union mask;
// load o_types scalars for union hits only (~0.95/thread) -> final mask.
// Phase A2: warp shfl-prefix compaction. Phase B: warp gathers its own hits.
// Phase C: plain-store warp partials, one sync, combine, epilogue.
__global__ void __launch_bounds__(TPB, 1) fused_kernel(
    const float* __restrict__ h_context,
    const float* __restrict__ l_local,
    const float* __restrict__ lambda_so,
    const int* __restrict__ center_o,
    const int* __restrict__ o_types,
    const unsigned int* __restrict__ adj,   // bool as 32-bit word (i32/f32 0|1)
    const unsigned int* __restrict__ two,
    float* __restrict__ out)
{
    __shared__ int   s_widx[NWARP][WCAP];
    __shared__ int   s_wcnt[NWARP];
    __shared__ float s_part[NWARP][DD];
    __shared__ float sv[DD];

    const int b    = blockIdx.x;
    const int tid  = threadIdx.x;
    const int w    = tid >> 5;     // warp id == output row r
    const int lane = tid & 31;

    // Epilogue operands resident early: thread tid's float2 of l_local[b]
    // is row (tid/32)=w, cols {2*lane, 2*lane+1}.
    const float2 ll = reinterpret_cast<const float2*>(
        l_local + (size_t)b * RR * DD)[tid];
    const int   co  = __ldg(&center_o[b]);
    const float lam = __ldg(&lambda_so[w * OO + co]);

    // ---- Phase A: stream adj+two only (8 front-batched LDG.128) ----
    // uint4 index u = g*1024 + tid (g = 0..3); element n = g*4096 + tid*4 + j.
    const uint4* a4 = reinterpret_cast<const uint4*>(adj + b * NN);
    const uint4* t4 = reinterpret_cast<const uint4*>(two + b * NN);

    uint4 av[4], tv[4];
    #pragma unroll
    for (int g = 0; g < 4; g++) av[g] = a4[g * 1024 + tid];
    #pragma unroll
    for (int g = 0; g < 4; g++) tv[g] = t4[g * 1024 + tid];

    unsigned um = 0;   // union (adj|two) bit mask, bit = g*4 + j
    #pragma unroll
    for (int g = 0; g < 4; g++) {
        um |= (unsigned)((av[g].x | tv[g].x) != 0u) << (g * 4 + 0);
        um |= (unsigned)((av[g].y | tv[g].y) != 0u) << (g * 4 + 1);
        um |= (unsigned)((av[g].z | tv[g].z) != 0u) << (g * 4 + 2);
        um |= (unsigned)((av[g].w | tv[g].w) != 0u) << (g * 4 + 3);
    }

    // Sparse o_types check: only union hits (~0.95 per thread).
    const int* otp = o_types + b * NN;
    unsigned hm = 0;
    {
        unsigned m = um;
        while (m) {
            int k = __ffs(m) - 1; m &= m - 1;
            int n = (k >> 2) * 4096 + tid * 4 + (k & 3);
            int v = __ldg(otp + n);
            hm |= (unsigned)(v == co) << k;
        }
    }

    // ---- Phase A2: warp-local compaction (shfl prefix; no atomics) ----
    int my = __popc(hm);
    int pre = my;
    #pragma unroll
    for (int o = 1; o < 32; o <<= 1) {
        int v = __shfl_up_sync(0xffffffffu, pre, o);
        if (lane >= o) pre += v;
    }
    const int wtot = __shfl_sync(0xffffffffu, pre, 31);   // warp hit count
    int p = pre - my;                                      // exclusive prefix
    unsigned m2 = hm;
    while (m2) {
        int k = __ffs(m2) - 1; m2 &= m2 - 1;
        int n = (k >> 2) * 4096 + tid * 4 + (k & 3);
        if (p < WCAP) s_widx[w][p] = n;
        p++;
    }
    __syncwarp();
    const int wcnt = (wtot < WCAP) ? wtot : WCAP;

    // ---- Phase B: warp gathers its own hits (starts immediately) ----
    const float2* ctx2 = reinterpret_cast<const float2*>(
        h_context + (size_t)b * NN * DD);
    float accx = 0.0f, accy = 0.0f;
    for (int bo = 0; bo < wcnt; bo += 4) {
        float2 xs[4];
        #pragma unroll
        for (int k = 0; k < 4; k++) {
            int i = bo + k;
            xs[k] = (i < wcnt)
                  ? __ldg(ctx2 + (size_t)s_widx[w][i] * (DD / 2) + lane)
                  : make_float2(0.0f, 0.0f);
        }
        #pragma unroll
        for (int k = 0; k < 4; k++) {
            float sq = xs[k].x * xs[k].x + xs[k].y * xs[k].y;
            #pragma unroll
            for (int o = 16; o; o >>= 1)
                sq += __shfl_xor_sync(0xffffffffu, sq, o);
            float rinv = rsqrtf(fmaxf(sq, 1e-12f));   // zero rows contribute 0
            accx += xs[k].x * rinv;
            accy += xs[k].y * rinv;
        }
    }
    s_part[w][2 * lane + 0] = accx;
    s_part[w][2 * lane + 1] = accy;
    if (lane == 0) s_wcnt[w] = wtot;
    __syncthreads();

    // ---- Phase C: combine 32 warp partials (64 threads), then epilogue ----
    if (tid < DD) {
        float s = 0.0f;
        #pragma unroll
        for (int ww = 0; ww < NWARP; ww++) s += s_part[ww][tid];
        sv[tid] = s;
    }
    __syncthreads();

    int c = s_wcnt[lane];
    #pragma unroll
    for (int o = 16; o; o >>= 1) c += __shfl_xor_sync(0xffffffffu, c, o);
    const float cval = (float)c;

    float sq = ll.x * ll.x + ll.y * ll.y;
    float dp = ll.x * sv[2 * lane] + ll.y * sv[2 * lane + 1];
    #pragma unroll
    for (int o = 16; o; o >>= 1) {
        sq += __shfl_xor_sync(0xffffffffu, sq, o);
        dp += __shfl_xor_sync(0xffffffffu, dp, o);
    }
    if (lane == 0) {
        float rinv = rsqrtf(fmaxf(sq, 1e-12f));
        float avg = dp * rinv / fmaxf(cval, 1e-9f);
        float wv = fmaxf(lam / fmaxf(cval, 1.0f), 0.0f) * (1.0f - avg);
        out[b * RR + w] = wv;
    }
}

extern "C" void kernel_launch(void* const* d_in, const int* in_sizes, int n_in,
                              void* d_out, int out_size) {
    const float*        l_local   = (const float*)d_in[0];
    const float*        h_context = (const float*)d_in[1];
    const float*        lambda_so = (const float*)d_in[2];
    const int*          center_o  = (const int*)d_in[3];
    const int*          o_types   = (const int*)d_in[4];
    const unsigned int* adj       = (const unsigned int*)d_in[5];
    const unsigned int* two       = (const unsigned int*)d_in[6];
    float*              out       = (float*)d_out;

    fused_kernel<<<BB, TPB>>>(h_context, l_local, lambda_so,
                              center_o, o_types, adj, two, out);
}